// round 13
// baseline (speedup 1.0000x reference)
#include <cuda_runtime.h>
#include <cuda_bf16.h>
#include <math.h>
#include <stdint.h>

#define BB   64
#define SS   512
#define EMB  768
#define HID  512
#define G4   2048      // 4*HID
#define NTAG 9
#define NROW (SS*BB)   // 32768
#define NCOL (2*G4)    // 4096

// ---------------- scratch (static device globals; no allocation) ----------------
__device__ float g_xp  [2u*SS*BB*G4];      // [dir][t][b][g]
__device__ float g_emis[SS*BB*NTAG];
__device__ float g_llh [BB];
__device__ float g_msum[BB];
__device__ unsigned g_cnt4[2][4];          // per-(direction, batch-quarter) arrival counters
__device__ __nv_bfloat16 g_xbf  [(size_t)NROW*EMB];     // 48 MB, rows = b*SS+t
__device__ __nv_bfloat16 g_wbf  [(size_t)NCOL*EMB];     // 6 MB
__device__ __nv_bfloat16 g_whhbf[2u*G4*HID];            // 8 MB [dir][row][k]
__device__ __nv_bfloat16 g_hallbf[2u*SS*BB*HID];        // 64 MB [dir][t][b][j]

// ======================= helpers =======================
__device__ __forceinline__ uint32_t smem_u32(const void* p) {
    uint32_t a;
    asm("{ .reg .u64 t; cvta.to.shared.u64 t, %1; cvt.u32.u64 %0, t; }" : "=r"(a) : "l"(p));
    return a;
}
__device__ __forceinline__ void cp_async16(uint32_t dst, const void* src) {
    asm volatile("cp.async.cg.shared.global [%0], [%1], 16;" :: "r"(dst), "l"(src) : "memory");
}
__device__ __forceinline__ void cp_commit() {
    asm volatile("cp.async.commit_group;" ::: "memory");
}
template <int N>
__device__ __forceinline__ void cp_waitn() {
    asm volatile("cp.async.wait_group %0;" :: "n"(N) : "memory");
}
__device__ __forceinline__ void cp_wait2() { cp_waitn<2>(); }
__device__ __forceinline__ void cp_wait1() { cp_waitn<1>(); }
__device__ __forceinline__ void cp_wait0() { cp_waitn<0>(); }
__device__ __forceinline__ void ldsm_x4(uint32_t& r0, uint32_t& r1, uint32_t& r2, uint32_t& r3,
                                        uint32_t addr) {
    asm volatile("ldmatrix.sync.aligned.m8n8.x4.shared.b16 {%0,%1,%2,%3}, [%4];"
                 : "=r"(r0), "=r"(r1), "=r"(r2), "=r"(r3) : "r"(addr));
}
__device__ __forceinline__ void mma_bf16(float* c, const uint32_t* a, const uint32_t* b) {
    asm volatile(
        "mma.sync.aligned.m16n8k16.row.col.f32.bf16.bf16.f32 "
        "{%0,%1,%2,%3}, {%4,%5,%6,%7}, {%8,%9}, {%0,%1,%2,%3};"
        : "+f"(c[0]), "+f"(c[1]), "+f"(c[2]), "+f"(c[3])
        : "r"(a[0]), "r"(a[1]), "r"(a[2]), "r"(a[3]), "r"(b[0]), "r"(b[1]));
}
__device__ __forceinline__ float tanh_ap(float x) {
    float y;
    asm("tanh.approx.f32 %0, %1;" : "=f"(y) : "f"(x));
    return y;
}
__device__ __forceinline__ float sig_ap(float x) { return 0.5f * tanh_ap(0.5f * x) + 0.5f; }
__device__ __forceinline__ void red_release_add(unsigned* p) {
    asm volatile("red.release.gpu.global.add.u32 [%0], %1;" :: "l"(p), "r"(1u) : "memory");
}
__device__ __forceinline__ unsigned ld_acquire(const unsigned* p) {
    unsigned v;
    asm volatile("ld.acquire.gpu.global.u32 %0, [%1];" : "=r"(v) : "l"(p) : "memory");
    return v;
}

// ---------------- K_init: zero barrier counters (replay-safe base) ----------------
__global__ void k_init()
{
    if (threadIdx.x < 8) ((unsigned*)g_cnt4)[threadIdx.x] = 0u;
}

// ---------------- K0: fp32 -> bf16 conversions ----------------
__global__ __launch_bounds__(256, 4) void k0_cvt_x(const float* __restrict__ xf)
{
    size_t n2 = (size_t)NROW * EMB / 2;
    for (size_t i = (size_t)blockIdx.x * 256 + threadIdx.x; i < n2;
         i += (size_t)gridDim.x * 256) {
        float2 v = ((const float2*)xf)[i];
        ((__nv_bfloat162*)g_xbf)[i] = __float22bfloat162_rn(v);
    }
}
__global__ __launch_bounds__(256, 4) void k0_cvt_w(const float* __restrict__ wf,
                                                   const float* __restrict__ wb)
{
    size_t n2 = (size_t)G4 * EMB / 2;
    for (size_t i = (size_t)blockIdx.x * 256 + threadIdx.x; i < n2;
         i += (size_t)gridDim.x * 256) {
        float2 v = ((const float2*)wf)[i];
        ((__nv_bfloat162*)g_wbf)[i] = __float22bfloat162_rn(v);
        float2 u = ((const float2*)wb)[i];
        ((__nv_bfloat162*)g_wbf)[n2 + i] = __float22bfloat162_rn(u);
    }
}
__global__ __launch_bounds__(256, 4) void k0_cvt_whh(const float* __restrict__ wf,
                                                     const float* __restrict__ wb)
{
    size_t n2 = (size_t)G4 * HID / 2;
    for (size_t i = (size_t)blockIdx.x * 256 + threadIdx.x; i < n2;
         i += (size_t)gridDim.x * 256) {
        float2 v = ((const float2*)wf)[i];
        ((__nv_bfloat162*)g_whhbf)[i] = __float22bfloat162_rn(v);
        float2 u = ((const float2*)wb)[i];
        ((__nv_bfloat162*)g_whhbf)[n2 + i] = __float22bfloat162_rn(u);
    }
}

// ---------------- K1: input projection, mma.sync bf16 HMMA, 3-stage pipeline ----------------
#define KC     64
#define NSTG   (EMB / KC)      // 12
#define LDA    72              // bf16 elements per padded row
#define TILE_BYTES (128 * LDA * 2)   // 18432

__global__ __launch_bounds__(256)
void k1_inproj(const float* __restrict__ bf, const float* __restrict__ bb2)
{
    extern __shared__ __align__(16) char sm1[];
    uint32_t sbase = smem_u32(sm1);
    __shared__ float sbias[128];

    const int tid  = threadIdx.x;
    const int lane = tid & 31;
    const int wid  = tid >> 5;
    const int m0 = blockIdx.y * 128;
    const int n0 = blockIdx.x * 128;

    if (tid < 128) {
        int n = n0 + tid;
        sbias[tid] = (n < G4) ? bf[n] : bb2[n - G4];
    }

    const __nv_bfloat16* gA = g_xbf + (size_t)m0 * EMB;
    const __nv_bfloat16* gB = g_wbf + (size_t)n0 * EMB;
    const int q0 = tid * 4;

    auto stage = [&](int s, int buf) {
        uint32_t sa = sbase + buf * 2 * TILE_BYTES;
        uint32_t sb = sa + TILE_BYTES;
#pragma unroll
        for (int i = 0; i < 4; ++i) {
            int q = q0 + i;
            int row = q >> 3, cc = q & 7;
            uint32_t off = (uint32_t)row * (LDA * 2) + cc * 16;
            cp_async16(sa + off, gA + (size_t)row * EMB + s * KC + cc * 8);
            cp_async16(sb + off, gB + (size_t)row * EMB + s * KC + cc * 8);
        }
        cp_commit();
    };

    float acc[16][4];
#pragma unroll
    for (int i = 0; i < 16; ++i)
#pragma unroll
        for (int j = 0; j < 4; ++j) acc[i][j] = 0.f;

    const int warp_m = wid >> 2;
    const int warp_n = wid & 3;
    const int m_w = warp_m * 64;
    const int n_w = warp_n * 32;

    stage(0, 0);
    stage(1, 1);

    for (int s = 0; s < NSTG; ++s) {
        int buf = s % 3;
        if (s + 2 < NSTG) { stage(s + 2, (s + 2) % 3); cp_wait2(); }
        else if (s + 1 < NSTG) cp_wait1();
        else cp_wait0();
        __syncthreads();

        uint32_t sa = sbase + buf * 2 * TILE_BYTES;
        uint32_t sb = sa + TILE_BYTES;

#pragma unroll
        for (int kk = 0; kk < KC / 16; ++kk) {
            const int k0 = kk * 16;
            uint32_t af[4][4];
#pragma unroll
            for (int mi = 0; mi < 4; ++mi) {
                uint32_t addr = sa + ((uint32_t)(m_w + mi * 16 + (lane & 15)) * (LDA * 2))
                                   + ((uint32_t)(k0 + (lane >> 4) * 8) * 2);
                ldsm_x4(af[mi][0], af[mi][1], af[mi][2], af[mi][3], addr);
            }
            uint32_t bfrg[4][2];
#pragma unroll
            for (int p = 0; p < 2; ++p) {
                uint32_t nrow = (uint32_t)(n_w + p * 16 + ((lane >> 4) & 1) * 8 + (lane & 7));
                uint32_t kcol = (uint32_t)(k0 + ((lane >> 3) & 1) * 8);
                uint32_t addr = sb + nrow * (LDA * 2) + kcol * 2;
                uint32_t r0, r1, r2, r3;
                ldsm_x4(r0, r1, r2, r3, addr);
                bfrg[p * 2 + 0][0] = r0; bfrg[p * 2 + 0][1] = r1;
                bfrg[p * 2 + 1][0] = r2; bfrg[p * 2 + 1][1] = r3;
            }
#pragma unroll
            for (int mi = 0; mi < 4; ++mi)
#pragma unroll
                for (int ni = 0; ni < 4; ++ni)
                    mma_bf16(acc[mi * 4 + ni], af[mi], bfrg[ni]);
        }
        __syncthreads();
    }

#pragma unroll
    for (int mi = 0; mi < 4; ++mi) {
#pragma unroll
        for (int ni = 0; ni < 4; ++ni) {
            int mbase = m0 + m_w + mi * 16 + (lane >> 2);
            int nbase = n0 + n_w + ni * 8 + 2 * (lane & 3);
            int dir = nbase >> 11, g = nbase & 2047;
            float bia0 = sbias[nbase - n0], bia1 = sbias[nbase - n0 + 1];
#pragma unroll
            for (int rr = 0; rr < 2; ++rr) {
                int m = mbase + rr * 8;
                int b = m >> 9, t = m & 511;
                float2 v;
                v.x = acc[mi * 4 + ni][rr * 2 + 0] + bia0;
                v.y = acc[mi * 4 + ni][rr * 2 + 1] + bia1;
                *(float2*)&g_xp[(((size_t)dir * SS + t) * BB + b) * G4 + g] = v;
            }
        }
    }
}

// ---------------- K2: persistent BiLSTM recurrence (dual-direction interleave) ----------------
// 64 CTAs; each CTA owns unit-group ug for BOTH directions. Per warp: two
// independent chains (fwd/bwd) interleaved so each handoff's propagate+detect
// latency is hidden behind the other direction's MMA, and bwd staging streams
// under fwd MMA. Release-add / acquire-load handoff, hybrid poll.
#define LDB 520    // bf16 per padded SMEM row (1040B, 16B-aligned, ldmatrix conflict-free)

__global__ __launch_bounds__(128, 1)
void k2_lstm_tc()
{
    extern __shared__ __align__(16) char sm2[];
    __nv_bfloat16* swb = (__nv_bfloat16*)sm2;          // [dir][32][LDB] weights
    __nv_bfloat16* shb = swb + 2 * 32 * LDB;           // [dir][64][LDB] h tiles
    const uint32_t sw_u0 = smem_u32(swb);
    const uint32_t sh_u0 = smem_u32(shb);

    const int ug  = blockIdx.x;                        // 0..63
    const int tid = threadIdx.x, lane = tid & 31, wid = tid >> 5;

    // load gate rows for BOTH directions (gl = gate*8 + ul), k-major
#pragma unroll
    for (int d = 0; d < 2; ++d) {
        const __nv_bfloat16* wsrc = g_whhbf + (size_t)d * G4 * HID;
        for (int i = tid; i < 32 * (HID / 8); i += 128) {
            int gl = i >> 6, cc = i & 63;
            int grow = (gl >> 3) * HID + ug * 8 + (gl & 7);
            *(uint4*)&swb[(size_t)d * 32 * LDB + gl * LDB + cc * 8] =
                *(const uint4*)&wsrc[(size_t)grow * HID + cc * 8];
        }
    }
    __syncthreads();   // weights visible; last CTA-wide sync

    float creg[2][4] = {{0.f,0.f,0.f,0.f},{0.f,0.f,0.f,0.f}};
    const int brow = wid * 16 + (lane >> 2);       // batch row (+0 / +8)
    const int ul0  = 2 * (lane & 3);
    const int jcol = ug * 8 + ul0;

    unsigned* cntp[2] = { &g_cnt4[0][wid], &g_cnt4[1][wid] };

    auto poll = [&](int d, unsigned tgt) {
        if (lane == 0) {
            int spins = 0;
            while ((int)(ld_acquire(cntp[d]) - tgt) < 0) {
                if (++spins > 64) __nanosleep(32);
            }
        }
        __syncwarp();
    };
    auto stage_dir = [&](int d, int t_prev) {
        const __nv_bfloat16* hsrc = g_hallbf + ((size_t)d * SS + t_prev) * BB * HID;
        uint32_t shd = sh_u0 + (uint32_t)d * 64 * LDB * 2;
#pragma unroll
        for (int g = 0; g < 4; ++g) {
#pragma unroll
            for (int i = 0; i < 8; ++i) {
                int q = i * 32 + lane;              // 0..255: 16 rows x 16 chunks of 16B
                int row = wid * 16 + (q >> 4), cc = q & 15;
                cp_async16(shd + (uint32_t)row * (LDB * 2) + (uint32_t)(g * 256 + cc * 16),
                           hsrc + (size_t)row * HID + g * 128 + cc * 8);
            }
            cp_commit();
        }
    };

    for (int s = 0; s < SS; ++s) {
        const int tf = s, tb = SS - 1 - s;

        // prefetch xp for both directions (barrier-independent)
        float2 xv[2][2][4];
#pragma unroll
        for (int d = 0; d < 2; ++d) {
            const int t = d ? tb : tf;
            const float* xpb = g_xp + (((size_t)d * SS + t) * BB) * G4;
#pragma unroll
            for (int r = 0; r < 2; ++r)
#pragma unroll
                for (int gate = 0; gate < 4; ++gate)
                    xv[d][r][gate] = __ldg((const float2*)&xpb[(size_t)(brow + r * 8) * G4
                                                               + gate * HID + jcol]);
        }

        float acc[4][4];
        const unsigned tgt = 64u * (unsigned)s;

        if (s > 0) {
            poll(0, tgt);
            stage_dir(0, tf - 1);      // groups 0..3 (pending 8..5 after bwd issue)
            poll(1, tgt);
            stage_dir(1, tb + 1);      // groups 4..7
        }

#pragma unroll
        for (int d = 0; d < 2; ++d) {
            const int t = d ? tb : tf;
#pragma unroll
            for (int a = 0; a < 4; ++a)
#pragma unroll
                for (int bq = 0; bq < 4; ++bq) acc[a][bq] = 0.f;

            if (s > 0) {
                uint32_t shd = sh_u0 + (uint32_t)d * 64 * LDB * 2;
                uint32_t swd = sw_u0 + (uint32_t)d * 32 * LDB * 2;
#pragma unroll
                for (int g = 0; g < 4; ++g) {
                    if (d == 0) {
                        if (g == 0) cp_waitn<7>();
                        else if (g == 1) cp_waitn<6>();
                        else if (g == 2) cp_waitn<5>();
                        else cp_waitn<4>();
                    } else {
                        if (g == 0) cp_waitn<3>();
                        else if (g == 1) cp_waitn<2>();
                        else if (g == 2) cp_waitn<1>();
                        else cp_waitn<0>();
                    }
                    __syncwarp();
#pragma unroll
                    for (int kq = 0; kq < 8; ++kq) {
                        const int k0 = g * 128 + kq * 16;
                        uint32_t af[4];
                        {
                            uint32_t addr = shd + (uint32_t)(wid * 16 + (lane & 15)) * (LDB * 2)
                                                 + (uint32_t)(k0 + (lane >> 4) * 8) * 2;
                            ldsm_x4(af[0], af[1], af[2], af[3], addr);
                        }
                        uint32_t bfrg[4][2];
#pragma unroll
                        for (int p = 0; p < 2; ++p) {
                            uint32_t nrow = (uint32_t)(p * 16 + ((lane >> 4) & 1) * 8 + (lane & 7));
                            uint32_t kcol = (uint32_t)(k0 + ((lane >> 3) & 1) * 8);
                            uint32_t addr = swd + nrow * (LDB * 2) + kcol * 2;
                            uint32_t r0, r1, r2, r3;
                            ldsm_x4(r0, r1, r2, r3, addr);
                            bfrg[p * 2 + 0][0] = r0; bfrg[p * 2 + 0][1] = r1;
                            bfrg[p * 2 + 1][0] = r2; bfrg[p * 2 + 1][1] = r3;
                        }
#pragma unroll
                        for (int ni = 0; ni < 4; ++ni) mma_bf16(acc[ni], af, bfrg[ni]);
                    }
                }
            }

            // add prefetched xp, register-local cell update (MUFU), store h
            __nv_bfloat16* hall = g_hallbf + ((size_t)d * SS + t) * BB * HID;
#pragma unroll
            for (int r = 0; r < 2; ++r) {
                int b = brow + r * 8;
                float hv[2];
#pragma unroll
                for (int e = 0; e < 2; ++e) {
                    int q = r * 2 + e;
                    float pi = acc[0][q] + (e ? xv[d][r][0].y : xv[d][r][0].x);
                    float pf = acc[1][q] + (e ? xv[d][r][1].y : xv[d][r][1].x);
                    float pg = acc[2][q] + (e ? xv[d][r][2].y : xv[d][r][2].x);
                    float po = acc[3][q] + (e ? xv[d][r][3].y : xv[d][r][3].x);
                    float i_ = sig_ap(pi);
                    float f_ = sig_ap(pf);
                    float g_ = tanh_ap(pg);
                    float o_ = sig_ap(po);
                    float c = f_ * creg[d][q] + i_ * g_;
                    creg[d][q] = c;
                    hv[e] = o_ * tanh_ap(c);
                }
                __nv_bfloat162 hb2 = __floats2bfloat162_rn(hv[0], hv[1]);
                *(__nv_bfloat162*)&hall[(size_t)b * HID + jcol] = hb2;
            }

            // publish this direction: release-add orders the h stores
            __syncwarp();
            if (lane == 0) red_release_add(cntp[d]);
        }
    }
}

// ---------------- K3: emissions (bf16 h) ----------------
__global__ __launch_bounds__(256, 1)
void k3_emis(const float* __restrict__ wout, const float* __restrict__ bout)
{
    __shared__ float sw[NTAG][2 * HID];
    for (int i = threadIdx.x; i < NTAG * 2 * HID; i += 256)
        sw[i / (2 * HID)][i % (2 * HID)] = wout[i];
    __syncthreads();

    int warp = blockIdx.x * 8 + (threadIdx.x >> 5);
    int lane = threadIdx.x & 31;
    int t = warp >> 6, b = warp & 63;

    const __nv_bfloat16* hf = g_hallbf + (((size_t)0 * SS + t) * BB + b) * HID;
    const __nv_bfloat16* hb = g_hallbf + (((size_t)1 * SS + t) * BB + b) * HID;

    float acc[NTAG];
#pragma unroll
    for (int q = 0; q < NTAG; ++q) acc[q] = 0.f;

    for (int k2 = lane; k2 < HID / 2; k2 += 32) {
        __nv_bfloat162 a2 = *(const __nv_bfloat162*)&hf[2 * k2];
        __nv_bfloat162 c2 = *(const __nv_bfloat162*)&hb[2 * k2];
        float f0 = __bfloat162float(a2.x), f1 = __bfloat162float(a2.y);
        float g0 = __bfloat162float(c2.x), g1 = __bfloat162float(c2.y);
#pragma unroll
        for (int q = 0; q < NTAG; ++q) {
            acc[q] = fmaf(f0, sw[q][2 * k2], acc[q]);
            acc[q] = fmaf(f1, sw[q][2 * k2 + 1], acc[q]);
            acc[q] = fmaf(g0, sw[q][HID + 2 * k2], acc[q]);
            acc[q] = fmaf(g1, sw[q][HID + 2 * k2 + 1], acc[q]);
        }
    }
#pragma unroll
    for (int q = 0; q < NTAG; ++q)
        for (int off = 16; off; off >>= 1)
            acc[q] += __shfl_down_sync(0xffffffffu, acc[q], off);
    if (lane == 0) {
#pragma unroll
        for (int q = 0; q < NTAG; ++q)
            g_emis[((size_t)t * BB + b) * NTAG + q] = acc[q] + bout[q];
    }
}

// ---------------- K4: CRF (fast exp/log) ----------------
__global__ __launch_bounds__(1024, 1)
void k4_crf(const int* __restrict__ mask, const int* __restrict__ tags,
            const float* __restrict__ st, const float* __restrict__ et,
            const float* __restrict__ tr)
{
    int w = (blockIdx.x * blockDim.x + threadIdx.x) >> 5;
    int lane = threadIdx.x & 31;
    if (w >= BB) return;
    const int b = w;
    const int* mb = mask + b * SS;
    const int* tg = tags + b * SS;

    float numpart = 0.f, mpart = 0.f;
    for (int t = lane; t < SS; t += 32) {
        float m = (float)mb[t];
        mpart += m;
        if (t >= 1)
            numpart += m * (tr[tg[t - 1] * NTAG + tg[t]] +
                            g_emis[((size_t)t * BB + b) * NTAG + tg[t]]);
    }
    for (int off = 16; off; off >>= 1) {
        numpart += __shfl_xor_sync(0xffffffffu, numpart, off);
        mpart   += __shfl_xor_sync(0xffffffffu, mpart, off);
    }

    float tc[NTAG];
#pragma unroll
    for (int j = 0; j < NTAG; ++j)
        tc[j] = (lane < NTAG) ? tr[j * NTAG + lane] : 0.f;

    float alpha = (lane < NTAG)
        ? st[lane] + g_emis[((size_t)0 * BB + b) * NTAG + lane]
        : -1e30f;

    for (int t = 1; t < SS; ++t) {
        float e = (lane < NTAG) ? g_emis[((size_t)t * BB + b) * NTAG + lane] : 0.f;
        float v[NTAG];
        float mx = -1e30f;
#pragma unroll
        for (int j = 0; j < NTAG; ++j) {
            v[j] = __shfl_sync(0xffffffffu, alpha, j) + tc[j];
            mx = fmaxf(mx, v[j]);
        }
        float sum = 0.f;
#pragma unroll
        for (int j = 0; j < NTAG; ++j) sum += __expf(v[j] - mx);
        float nxt = mx + __logf(sum) + e;
        alpha = (mb[t] > 0) ? nxt : alpha;
    }

    float vden = (lane < NTAG) ? alpha + et[lane] : -1e30f;
    float mx = vden;
    for (int off = 16; off; off >>= 1) mx = fmaxf(mx, __shfl_xor_sync(0xffffffffu, mx, off));
    float se = (lane < NTAG) ? __expf(vden - mx) : 0.f;
    for (int off = 16; off; off >>= 1) se += __shfl_xor_sync(0xffffffffu, se, off);
    float den = mx + __logf(se);

    if (lane == 0) {
        int t0 = tg[0];
        float num = numpart + st[t0] + g_emis[((size_t)0 * BB + b) * NTAG + t0];
        int li = (int)(mpart + 0.5f) - 1;
        num += et[tg[li]];
        g_llh[b]  = num - den;
        g_msum[b] = mpart;
    }
}

// ---------------- K5: deterministic final reduce ----------------
__global__ void k5_reduce(float* out)
{
    if (threadIdx.x == 0 && blockIdx.x == 0) {
        float sn = 0.f, sm = 0.f;
        for (int b = 0; b < BB; ++b) { sn += g_llh[b]; sm += g_msum[b]; }
        out[0] = -(sn / sm);
    }
}

// ---------------- launch ----------------
extern "C" void kernel_launch(void* const* d_in, const int* in_sizes, int n_in,
                              void* d_out, int out_size)
{
    const float* x    = (const float*)d_in[0];
    const int*   mask = (const int*)  d_in[1];
    const int*   tags = (const int*)  d_in[2];
    const float* wihf = (const float*)d_in[3];
    const float* whhf = (const float*)d_in[4];
    const float* bf   = (const float*)d_in[5];
    const float* wihb = (const float*)d_in[6];
    const float* whhb = (const float*)d_in[7];
    const float* bb2  = (const float*)d_in[8];
    const float* wout = (const float*)d_in[9];
    const float* bout = (const float*)d_in[10];
    const float* st   = (const float*)d_in[11];
    const float* et   = (const float*)d_in[12];
    const float* tr   = (const float*)d_in[13];
    float* out = (float*)d_out;

    const int smem1 = 6 * TILE_BYTES;                         // 110592: 3-stage A|B
    const int smem2 = 192 * LDB * (int)sizeof(__nv_bfloat16); // 199680: dual-dir weights + h tiles
    static int inited = 0;
    if (!inited) {
        cudaFuncSetAttribute(k1_inproj, cudaFuncAttributeMaxDynamicSharedMemorySize, smem1);
        cudaFuncSetAttribute(k2_lstm_tc, cudaFuncAttributeMaxDynamicSharedMemorySize, smem2);
        inited = 1;
    }

    k_init<<<1, 32>>>();
    k0_cvt_x<<<2048, 256>>>(x);
    k0_cvt_w<<<512, 256>>>(wihf, wihb);
    k0_cvt_whh<<<512, 256>>>(whhf, whhb);
    k1_inproj<<<dim3(NCOL / 128, NROW / 128), 256, smem1>>>(bf, bb2);
    k2_lstm_tc<<<64, 128, smem2>>>();
    k3_emis<<<NROW / 8, 256>>>(wout, bout);
    k4_crf<<<2, 1024>>>(mask, tags, st, et, tr);
    k5_reduce<<<1, 32>>>(out);
}

// round 15
// speedup vs baseline: 1.2916x; 1.2916x over previous
#include <cuda_runtime.h>
#include <cuda_bf16.h>
#include <math.h>
#include <stdint.h>

#define BB   64
#define SS   512
#define EMB  768
#define HID  512
#define G4   2048      // 4*HID
#define NTAG 9
#define NROW (SS*BB)   // 32768
#define NCOL (2*G4)    // 4096

// ---------------- scratch (static device globals; no allocation) ----------------
__device__ float g_xp  [2u*SS*BB*G4];      // [dir][t][b][g]
__device__ float g_emis[SS*BB*NTAG];
__device__ float g_llh [BB];
__device__ float g_msum[BB];
__device__ unsigned g_cnt4[2][4];          // per-(direction, batch-quarter) arrival counters
__device__ __nv_bfloat16 g_xbf  [(size_t)NROW*EMB];     // 48 MB, rows = b*SS+t
__device__ __nv_bfloat16 g_wbf  [(size_t)NCOL*EMB];     // 6 MB
__device__ __nv_bfloat16 g_whhbf[2u*G4*HID];            // 8 MB [dir][row][k]
__device__ __nv_bfloat16 g_hallbf[2u*SS*BB*HID];        // 64 MB [dir][t][b][j]

// ======================= helpers =======================
__device__ __forceinline__ uint32_t smem_u32(const void* p) {
    uint32_t a;
    asm("{ .reg .u64 t; cvta.to.shared.u64 t, %1; cvt.u32.u64 %0, t; }" : "=r"(a) : "l"(p));
    return a;
}
__device__ __forceinline__ void cp_async16(uint32_t dst, const void* src) {
    asm volatile("cp.async.cg.shared.global [%0], [%1], 16;" :: "r"(dst), "l"(src) : "memory");
}
__device__ __forceinline__ void cp_commit() {
    asm volatile("cp.async.commit_group;" ::: "memory");
}
template <int N>
__device__ __forceinline__ void cp_waitn() {
    asm volatile("cp.async.wait_group %0;" :: "n"(N) : "memory");
}
__device__ __forceinline__ void cp_wait2() { cp_waitn<2>(); }
__device__ __forceinline__ void cp_wait1() { cp_waitn<1>(); }
__device__ __forceinline__ void cp_wait0() { cp_waitn<0>(); }
__device__ __forceinline__ void ldsm_x4(uint32_t& r0, uint32_t& r1, uint32_t& r2, uint32_t& r3,
                                        uint32_t addr) {
    asm volatile("ldmatrix.sync.aligned.m8n8.x4.shared.b16 {%0,%1,%2,%3}, [%4];"
                 : "=r"(r0), "=r"(r1), "=r"(r2), "=r"(r3) : "r"(addr));
}
__device__ __forceinline__ void mma_bf16(float* c, const uint32_t* a, const uint32_t* b) {
    asm volatile(
        "mma.sync.aligned.m16n8k16.row.col.f32.bf16.bf16.f32 "
        "{%0,%1,%2,%3}, {%4,%5,%6,%7}, {%8,%9}, {%0,%1,%2,%3};"
        : "+f"(c[0]), "+f"(c[1]), "+f"(c[2]), "+f"(c[3])
        : "r"(a[0]), "r"(a[1]), "r"(a[2]), "r"(a[3]), "r"(b[0]), "r"(b[1]));
}
__device__ __forceinline__ float tanh_ap(float x) {
    float y;
    asm("tanh.approx.f32 %0, %1;" : "=f"(y) : "f"(x));
    return y;
}
__device__ __forceinline__ float sig_ap(float x) { return 0.5f * tanh_ap(0.5f * x) + 0.5f; }
__device__ __forceinline__ void red_release_add(unsigned* p) {
    asm volatile("red.release.gpu.global.add.u32 [%0], %1;" :: "l"(p), "r"(1u) : "memory");
}
__device__ __forceinline__ unsigned ld_acquire(const unsigned* p) {
    unsigned v;
    asm volatile("ld.acquire.gpu.global.u32 %0, [%1];" : "=r"(v) : "l"(p) : "memory");
    return v;
}

// ---------------- K_init: zero barrier counters (replay-safe base) ----------------
__global__ void k_init()
{
    if (threadIdx.x < 8) ((unsigned*)g_cnt4)[threadIdx.x] = 0u;
}

// ---------------- K0: fp32 -> bf16 conversions ----------------
__global__ __launch_bounds__(256, 4) void k0_cvt_x(const float* __restrict__ xf)
{
    size_t n4 = (size_t)NROW * EMB / 4;
    for (size_t i = (size_t)blockIdx.x * 256 + threadIdx.x; i < n4;
         i += (size_t)gridDim.x * 256) {
        float4 v = ((const float4*)xf)[i];
        union { __nv_bfloat162 b2[2]; uint2 u2; } o;
        o.b2[0] = __floats2bfloat162_rn(v.x, v.y);
        o.b2[1] = __floats2bfloat162_rn(v.z, v.w);
        ((uint2*)g_xbf)[i] = o.u2;
    }
}
__global__ __launch_bounds__(256, 4) void k0_cvt_w(const float* __restrict__ wf,
                                                   const float* __restrict__ wb)
{
    size_t n2 = (size_t)G4 * EMB / 2;
    for (size_t i = (size_t)blockIdx.x * 256 + threadIdx.x; i < n2;
         i += (size_t)gridDim.x * 256) {
        float2 v = ((const float2*)wf)[i];
        ((__nv_bfloat162*)g_wbf)[i] = __float22bfloat162_rn(v);
        float2 u = ((const float2*)wb)[i];
        ((__nv_bfloat162*)g_wbf)[n2 + i] = __float22bfloat162_rn(u);
    }
}
__global__ __launch_bounds__(256, 4) void k0_cvt_whh(const float* __restrict__ wf,
                                                     const float* __restrict__ wb)
{
    size_t n2 = (size_t)G4 * HID / 2;
    for (size_t i = (size_t)blockIdx.x * 256 + threadIdx.x; i < n2;
         i += (size_t)gridDim.x * 256) {
        float2 v = ((const float2*)wf)[i];
        ((__nv_bfloat162*)g_whhbf)[i] = __float22bfloat162_rn(v);
        float2 u = ((const float2*)wb)[i];
        ((__nv_bfloat162*)g_whhbf)[n2 + i] = __float22bfloat162_rn(u);
    }
}

// ---------------- K1: input projection, mma.sync bf16 HMMA, 3-stage pipeline ----------------
#define KC     64
#define NSTG   (EMB / KC)      // 12
#define LDA    72              // bf16 elements per padded row
#define TILE_BYTES (128 * LDA * 2)   // 18432

__global__ __launch_bounds__(256)
void k1_inproj(const float* __restrict__ bf, const float* __restrict__ bb2)
{
    extern __shared__ __align__(16) char sm1[];
    uint32_t sbase = smem_u32(sm1);
    __shared__ float sbias[128];

    const int tid  = threadIdx.x;
    const int lane = tid & 31;
    const int wid  = tid >> 5;
    const int m0 = blockIdx.y * 128;
    const int n0 = blockIdx.x * 128;

    if (tid < 128) {
        int n = n0 + tid;
        sbias[tid] = (n < G4) ? bf[n] : bb2[n - G4];
    }

    const __nv_bfloat16* gA = g_xbf + (size_t)m0 * EMB;
    const __nv_bfloat16* gB = g_wbf + (size_t)n0 * EMB;
    const int q0 = tid * 4;

    auto stage = [&](int s, int buf) {
        uint32_t sa = sbase + buf * 2 * TILE_BYTES;
        uint32_t sb = sa + TILE_BYTES;
#pragma unroll
        for (int i = 0; i < 4; ++i) {
            int q = q0 + i;
            int row = q >> 3, cc = q & 7;
            uint32_t off = (uint32_t)row * (LDA * 2) + cc * 16;
            cp_async16(sa + off, gA + (size_t)row * EMB + s * KC + cc * 8);
            cp_async16(sb + off, gB + (size_t)row * EMB + s * KC + cc * 8);
        }
        cp_commit();
    };

    float acc[16][4];
#pragma unroll
    for (int i = 0; i < 16; ++i)
#pragma unroll
        for (int j = 0; j < 4; ++j) acc[i][j] = 0.f;

    const int warp_m = wid >> 2;
    const int warp_n = wid & 3;
    const int m_w = warp_m * 64;
    const int n_w = warp_n * 32;

    stage(0, 0);
    stage(1, 1);

    for (int s = 0; s < NSTG; ++s) {
        int buf = s % 3;
        if (s + 2 < NSTG) { stage(s + 2, (s + 2) % 3); cp_wait2(); }
        else if (s + 1 < NSTG) cp_wait1();
        else cp_wait0();
        __syncthreads();

        uint32_t sa = sbase + buf * 2 * TILE_BYTES;
        uint32_t sb = sa + TILE_BYTES;

#pragma unroll
        for (int kk = 0; kk < KC / 16; ++kk) {
            const int k0 = kk * 16;
            uint32_t af[4][4];
#pragma unroll
            for (int mi = 0; mi < 4; ++mi) {
                uint32_t addr = sa + ((uint32_t)(m_w + mi * 16 + (lane & 15)) * (LDA * 2))
                                   + ((uint32_t)(k0 + (lane >> 4) * 8) * 2);
                ldsm_x4(af[mi][0], af[mi][1], af[mi][2], af[mi][3], addr);
            }
            uint32_t bfrg[4][2];
#pragma unroll
            for (int p = 0; p < 2; ++p) {
                uint32_t nrow = (uint32_t)(n_w + p * 16 + ((lane >> 4) & 1) * 8 + (lane & 7));
                uint32_t kcol = (uint32_t)(k0 + ((lane >> 3) & 1) * 8);
                uint32_t addr = sb + nrow * (LDA * 2) + kcol * 2;
                uint32_t r0, r1, r2, r3;
                ldsm_x4(r0, r1, r2, r3, addr);
                bfrg[p * 2 + 0][0] = r0; bfrg[p * 2 + 0][1] = r1;
                bfrg[p * 2 + 1][0] = r2; bfrg[p * 2 + 1][1] = r3;
            }
#pragma unroll
            for (int mi = 0; mi < 4; ++mi)
#pragma unroll
                for (int ni = 0; ni < 4; ++ni)
                    mma_bf16(acc[mi * 4 + ni], af[mi], bfrg[ni]);
        }
        __syncthreads();
    }

#pragma unroll
    for (int mi = 0; mi < 4; ++mi) {
#pragma unroll
        for (int ni = 0; ni < 4; ++ni) {
            int mbase = m0 + m_w + mi * 16 + (lane >> 2);
            int nbase = n0 + n_w + ni * 8 + 2 * (lane & 3);
            int dir = nbase >> 11, g = nbase & 2047;
            float bia0 = sbias[nbase - n0], bia1 = sbias[nbase - n0 + 1];
#pragma unroll
            for (int rr = 0; rr < 2; ++rr) {
                int m = mbase + rr * 8;
                int b = m >> 9, t = m & 511;
                float2 v;
                v.x = acc[mi * 4 + ni][rr * 2 + 0] + bia0;
                v.y = acc[mi * 4 + ni][rr * 2 + 1] + bia1;
                *(float2*)&g_xp[(((size_t)dir * SS + t) * BB + b) * G4 + g] = v;
            }
        }
    }
}

// ---------------- K2: persistent BiLSTM recurrence (round-12 proven version) ----------------
// Four independent warp-level recurrence chains per CTA (batch quarters);
// release-add / acquire-load handoff, hybrid poll; h staging in 4 k-chunks
// overlapped with the HMMA chain.
#define LDB 520    // bf16 per padded SMEM row (1040B, 16B-aligned, ldmatrix conflict-free)

__global__ __launch_bounds__(128, 1)
void k2_lstm_tc()
{
    extern __shared__ __align__(16) char sm2[];
    __nv_bfloat16* swb = (__nv_bfloat16*)sm2;      // [32][LDB] weights (persistent, read-only after load)
    __nv_bfloat16* shb = swb + 32 * LDB;           // [64][LDB] h tile; warp w owns rows [16w,16w+16)
    const uint32_t sw_u = smem_u32(swb);
    const uint32_t sh_u = smem_u32(shb);

    const int dir = blockIdx.x >> 6;
    const int ug  = blockIdx.x & 63;
    const int tid = threadIdx.x, lane = tid & 31, wid = tid >> 5;

    // load this CTA's 32 gate rows (gl = gate*8 + ul), k-major
    const __nv_bfloat16* wsrc = g_whhbf + (size_t)dir * G4 * HID;
    for (int i = tid; i < 32 * (HID / 8); i += 128) {
        int gl = i >> 6, cc = i & 63;
        int grow = (gl >> 3) * HID + ug * 8 + (gl & 7);
        *(uint4*)&swb[gl * LDB + cc * 8] = *(const uint4*)&wsrc[(size_t)grow * HID + cc * 8];
    }
    __syncthreads();   // weights visible to all warps; last CTA-wide sync

    float creg[4] = {0.f, 0.f, 0.f, 0.f};          // cell state, [r*2+e], register-resident
    const int brow = wid * 16 + (lane >> 2);       // batch row (+0 / +8)
    const int ul0  = 2 * (lane & 3);               // unit pair within group
    const int jcol = ug * 8 + ul0;                 // global hidden index (even)

    unsigned* cnt = &g_cnt4[dir][wid];

    for (int s = 0; s < SS; ++s) {
        const int t = dir ? (SS - 1 - s) : s;

        // prefetch xp (barrier-independent) — latency hidden behind the wait
        const float* xpb = g_xp + (((size_t)dir * SS + t) * BB) * G4;
        float2 xv[2][4];
#pragma unroll
        for (int r = 0; r < 2; ++r)
#pragma unroll
            for (int gate = 0; gate < 4; ++gate)
                xv[r][gate] = __ldg((const float2*)&xpb[(size_t)(brow + r * 8) * G4
                                                        + gate * HID + jcol]);

        float acc[4][4];                            // [gate][r*2+e]
#pragma unroll
        for (int a = 0; a < 4; ++a)
#pragma unroll
            for (int bq = 0; bq < 4; ++bq) acc[a][bq] = 0.f;

        if (s > 0) {
            // wait: all 64 counterpart warps (same wid) published h(s-1)
            if (lane == 0) {
                const unsigned tgt = 64u * (unsigned)s;
                int spins = 0;
                while ((int)(ld_acquire(cnt) - tgt) < 0) {
                    if (++spins > 64) __nanosleep(32);   // yield under skew; no unbounded hard spin
                }
            }
            __syncwarp();

            // stage own 16 batch rows (16KB) in 4 k-chunks; all issued now,
            // each chunk's completion awaited just before its MMA block.
            const int t_prev = dir ? (t + 1) : (t - 1);
            const __nv_bfloat16* hsrc = g_hallbf + ((size_t)dir * SS + t_prev) * BB * HID;
#pragma unroll
            for (int g = 0; g < 4; ++g) {
#pragma unroll
                for (int i = 0; i < 8; ++i) {
                    int q = i * 32 + lane;          // 0..255: 16 rows x 16 chunks of 16B
                    int row = wid * 16 + (q >> 4), cc = q & 15;
                    cp_async16(sh_u + (uint32_t)row * (LDB * 2) + (uint32_t)(g * 256 + cc * 16),
                               hsrc + (size_t)row * HID + g * 128 + cc * 8);
                }
                cp_commit();
            }

#pragma unroll
            for (int g = 0; g < 4; ++g) {
                if (g == 0) cp_waitn<3>();
                else if (g == 1) cp_waitn<2>();
                else if (g == 2) cp_waitn<1>();
                else cp_waitn<0>();
                __syncwarp();
#pragma unroll
                for (int kq = 0; kq < 8; ++kq) {
                    const int k0 = g * 128 + kq * 16;
                    uint32_t af[4];
                    {
                        uint32_t addr = sh_u + (uint32_t)(wid * 16 + (lane & 15)) * (LDB * 2)
                                             + (uint32_t)(k0 + (lane >> 4) * 8) * 2;
                        ldsm_x4(af[0], af[1], af[2], af[3], addr);
                    }
                    uint32_t bfrg[4][2];
#pragma unroll
                    for (int p = 0; p < 2; ++p) {
                        uint32_t nrow = (uint32_t)(p * 16 + ((lane >> 4) & 1) * 8 + (lane & 7));
                        uint32_t kcol = (uint32_t)(k0 + ((lane >> 3) & 1) * 8);
                        uint32_t addr = sw_u + nrow * (LDB * 2) + kcol * 2;
                        uint32_t r0, r1, r2, r3;
                        ldsm_x4(r0, r1, r2, r3, addr);
                        bfrg[p * 2 + 0][0] = r0; bfrg[p * 2 + 0][1] = r1;
                        bfrg[p * 2 + 1][0] = r2; bfrg[p * 2 + 1][1] = r3;
                    }
#pragma unroll
                    for (int ni = 0; ni < 4; ++ni) mma_bf16(acc[ni], af, bfrg[ni]);
                }
            }
        }

        // add prefetched xp, register-local cell update (MUFU), store h
        __nv_bfloat16* hall = g_hallbf + ((size_t)dir * SS + t) * BB * HID;
#pragma unroll
        for (int r = 0; r < 2; ++r) {
            int b = brow + r * 8;
            float hv[2];
#pragma unroll
            for (int e = 0; e < 2; ++e) {
                int q = r * 2 + e;
                float pi = acc[0][q] + (e ? xv[r][0].y : xv[r][0].x);
                float pf = acc[1][q] + (e ? xv[r][1].y : xv[r][1].x);
                float pg = acc[2][q] + (e ? xv[r][2].y : xv[r][2].x);
                float po = acc[3][q] + (e ? xv[r][3].y : xv[r][3].x);
                float i_ = sig_ap(pi);
                float f_ = sig_ap(pf);
                float g_ = tanh_ap(pg);
                float o_ = sig_ap(po);
                float c = f_ * creg[q] + i_ * g_;
                creg[q] = c;
                hv[e] = o_ * tanh_ap(c);
            }
            __nv_bfloat162 hb2 = __floats2bfloat162_rn(hv[0], hv[1]);
            *(__nv_bfloat162*)&hall[(size_t)b * HID + jcol] = hb2;
        }

        // publish: release-add orders the h stores, fire-and-forget, no MEMBAR
        __syncwarp();
        if (lane == 0) red_release_add(cnt);
    }
}

// ---------------- K3: emissions (bf16 h) ----------------
__global__ __launch_bounds__(256, 1)
void k3_emis(const float* __restrict__ wout, const float* __restrict__ bout)
{
    __shared__ float sw[NTAG][2 * HID];
    for (int i = threadIdx.x; i < NTAG * 2 * HID; i += 256)
        sw[i / (2 * HID)][i % (2 * HID)] = wout[i];
    __syncthreads();

    int warp = blockIdx.x * 8 + (threadIdx.x >> 5);
    int lane = threadIdx.x & 31;
    int t = warp >> 6, b = warp & 63;

    const __nv_bfloat16* hf = g_hallbf + (((size_t)0 * SS + t) * BB + b) * HID;
    const __nv_bfloat16* hb = g_hallbf + (((size_t)1 * SS + t) * BB + b) * HID;

    float acc[NTAG];
#pragma unroll
    for (int q = 0; q < NTAG; ++q) acc[q] = 0.f;

    for (int k2 = lane; k2 < HID / 2; k2 += 32) {
        __nv_bfloat162 a2 = *(const __nv_bfloat162*)&hf[2 * k2];
        __nv_bfloat162 c2 = *(const __nv_bfloat162*)&hb[2 * k2];
        float f0 = __bfloat162float(a2.x), f1 = __bfloat162float(a2.y);
        float g0 = __bfloat162float(c2.x), g1 = __bfloat162float(c2.y);
#pragma unroll
        for (int q = 0; q < NTAG; ++q) {
            acc[q] = fmaf(f0, sw[q][2 * k2], acc[q]);
            acc[q] = fmaf(f1, sw[q][2 * k2 + 1], acc[q]);
            acc[q] = fmaf(g0, sw[q][HID + 2 * k2], acc[q]);
            acc[q] = fmaf(g1, sw[q][HID + 2 * k2 + 1], acc[q]);
        }
    }
#pragma unroll
    for (int q = 0; q < NTAG; ++q)
        for (int off = 16; off; off >>= 1)
            acc[q] += __shfl_down_sync(0xffffffffu, acc[q], off);
    if (lane == 0) {
#pragma unroll
        for (int q = 0; q < NTAG; ++q)
            g_emis[((size_t)t * BB + b) * NTAG + q] = acc[q] + bout[q];
    }
}

// ---------------- K4: CRF (fast exp/log; 1 warp per CTA, 64 CTAs -> MUFU spread) ----------------
__global__ __launch_bounds__(32, 1)
void k4_crf(const int* __restrict__ mask, const int* __restrict__ tags,
            const float* __restrict__ st, const float* __restrict__ et,
            const float* __restrict__ tr)
{
    const int b = blockIdx.x;          // 0..63
    const int lane = threadIdx.x & 31;
    const int* mb = mask + b * SS;
    const int* tg = tags + b * SS;

    float numpart = 0.f, mpart = 0.f;
    for (int t = lane; t < SS; t += 32) {
        float m = (float)mb[t];
        mpart += m;
        if (t >= 1)
            numpart += m * (tr[tg[t - 1] * NTAG + tg[t]] +
                            g_emis[((size_t)t * BB + b) * NTAG + tg[t]]);
    }
    for (int off = 16; off; off >>= 1) {
        numpart += __shfl_xor_sync(0xffffffffu, numpart, off);
        mpart   += __shfl_xor_sync(0xffffffffu, mpart, off);
    }

    float tc[NTAG];
#pragma unroll
    for (int j = 0; j < NTAG; ++j)
        tc[j] = (lane < NTAG) ? tr[j * NTAG + lane] : 0.f;

    float alpha = (lane < NTAG)
        ? st[lane] + g_emis[((size_t)0 * BB + b) * NTAG + lane]
        : -1e30f;

    for (int t = 1; t < SS; ++t) {
        float e = (lane < NTAG) ? g_emis[((size_t)t * BB + b) * NTAG + lane] : 0.f;
        float v[NTAG];
        float mx = -1e30f;
#pragma unroll
        for (int j = 0; j < NTAG; ++j) {
            v[j] = __shfl_sync(0xffffffffu, alpha, j) + tc[j];
            mx = fmaxf(mx, v[j]);
        }
        float sum = 0.f;
#pragma unroll
        for (int j = 0; j < NTAG; ++j) sum += __expf(v[j] - mx);
        float nxt = mx + __logf(sum) + e;
        alpha = (mb[t] > 0) ? nxt : alpha;
    }

    float vden = (lane < NTAG) ? alpha + et[lane] : -1e30f;
    float mx = vden;
    for (int off = 16; off; off >>= 1) mx = fmaxf(mx, __shfl_xor_sync(0xffffffffu, mx, off));
    float se = (lane < NTAG) ? __expf(vden - mx) : 0.f;
    for (int off = 16; off; off >>= 1) se += __shfl_xor_sync(0xffffffffu, se, off);
    float den = mx + __logf(se);

    if (lane == 0) {
        int t0 = tg[0];
        float num = numpart + st[t0] + g_emis[((size_t)0 * BB + b) * NTAG + t0];
        int li = (int)(mpart + 0.5f) - 1;
        num += et[tg[li]];
        g_llh[b]  = num - den;
        g_msum[b] = mpart;
    }
}

// ---------------- K5: deterministic final reduce ----------------
__global__ void k5_reduce(float* out)
{
    if (threadIdx.x == 0 && blockIdx.x == 0) {
        float sn = 0.f, sm = 0.f;
        for (int b = 0; b < BB; ++b) { sn += g_llh[b]; sm += g_msum[b]; }
        out[0] = -(sn / sm);
    }
}

// ---------------- launch ----------------
extern "C" void kernel_launch(void* const* d_in, const int* in_sizes, int n_in,
                              void* d_out, int out_size)
{
    const float* x    = (const float*)d_in[0];
    const int*   mask = (const int*)  d_in[1];
    const int*   tags = (const int*)  d_in[2];
    const float* wihf = (const float*)d_in[3];
    const float* whhf = (const float*)d_in[4];
    const float* bf   = (const float*)d_in[5];
    const float* wihb = (const float*)d_in[6];
    const float* whhb = (const float*)d_in[7];
    const float* bb2  = (const float*)d_in[8];
    const float* wout = (const float*)d_in[9];
    const float* bout = (const float*)d_in[10];
    const float* st   = (const float*)d_in[11];
    const float* et   = (const float*)d_in[12];
    const float* tr   = (const float*)d_in[13];
    float* out = (float*)d_out;

    const int smem1 = 6 * TILE_BYTES;                        // 110592: 3-stage A|B
    const int smem2 = 96 * LDB * (int)sizeof(__nv_bfloat16); // 99840
    static int inited = 0;
    if (!inited) {
        cudaFuncSetAttribute(k1_inproj, cudaFuncAttributeMaxDynamicSharedMemorySize, smem1);
        cudaFuncSetAttribute(k2_lstm_tc, cudaFuncAttributeMaxDynamicSharedMemorySize, smem2);
        inited = 1;
    }

    k_init<<<1, 32>>>();
    k0_cvt_x<<<2048, 256>>>(x);
    k0_cvt_w<<<512, 256>>>(wihf, wihb);
    k0_cvt_whh<<<512, 256>>>(whhf, whhb);
    k1_inproj<<<dim3(NCOL / 128, NROW / 128), 256, smem1>>>(bf, bb2);
    k2_lstm_tc<<<128, 128, smem2>>>();
    k3_emis<<<NROW / 8, 256>>>(wout, bout);
    k4_crf<<<BB, 32>>>(mask, tags, st, et, tr);
    k5_reduce<<<1, 32>>>(out);
}

// round 16
// speedup vs baseline: 1.3234x; 1.0246x over previous
#include <cuda_runtime.h>
#include <cuda_bf16.h>
#include <math.h>
#include <stdint.h>

#define BB   64
#define SS   512
#define EMB  768
#define HID  512
#define G4   2048      // 4*HID
#define NTAG 9
#define NROW (SS*BB)   // 32768
#define NCOL (2*G4)    // 4096

// ---------------- scratch (static device globals; no allocation) ----------------
__device__ __nv_bfloat16 g_xpbf[2u*SS*BB*G4];          // 256 MB [dir][t][b][g]
__device__ float g_emis[SS*BB*NTAG];
__device__ float g_llh [BB];
__device__ float g_msum[BB];
__device__ unsigned g_cnt4[2][4];          // per-(direction, batch-quarter) arrival counters
__device__ __nv_bfloat16 g_xbf  [(size_t)NROW*EMB];     // 48 MB, rows = b*SS+t
__device__ __nv_bfloat16 g_wbf  [(size_t)NCOL*EMB];     // 6 MB
__device__ __nv_bfloat16 g_whhbf[2u*G4*HID];            // 8 MB [dir][row][k]
__device__ __nv_bfloat16 g_hallbf[2u*SS*BB*HID];        // 64 MB [dir][t][b][j]

// ======================= helpers =======================
__device__ __forceinline__ uint32_t smem_u32(const void* p) {
    uint32_t a;
    asm("{ .reg .u64 t; cvta.to.shared.u64 t, %1; cvt.u32.u64 %0, t; }" : "=r"(a) : "l"(p));
    return a;
}
__device__ __forceinline__ void cp_async16(uint32_t dst, const void* src) {
    asm volatile("cp.async.cg.shared.global [%0], [%1], 16;" :: "r"(dst), "l"(src) : "memory");
}
__device__ __forceinline__ void cp_commit() {
    asm volatile("cp.async.commit_group;" ::: "memory");
}
template <int N>
__device__ __forceinline__ void cp_waitn() {
    asm volatile("cp.async.wait_group %0;" :: "n"(N) : "memory");
}
__device__ __forceinline__ void cp_wait2() { cp_waitn<2>(); }
__device__ __forceinline__ void cp_wait1() { cp_waitn<1>(); }
__device__ __forceinline__ void cp_wait0() { cp_waitn<0>(); }
__device__ __forceinline__ void ldsm_x4(uint32_t& r0, uint32_t& r1, uint32_t& r2, uint32_t& r3,
                                        uint32_t addr) {
    asm volatile("ldmatrix.sync.aligned.m8n8.x4.shared.b16 {%0,%1,%2,%3}, [%4];"
                 : "=r"(r0), "=r"(r1), "=r"(r2), "=r"(r3) : "r"(addr));
}
__device__ __forceinline__ void mma_bf16(float* c, const uint32_t* a, const uint32_t* b) {
    asm volatile(
        "mma.sync.aligned.m16n8k16.row.col.f32.bf16.bf16.f32 "
        "{%0,%1,%2,%3}, {%4,%5,%6,%7}, {%8,%9}, {%0,%1,%2,%3};"
        : "+f"(c[0]), "+f"(c[1]), "+f"(c[2]), "+f"(c[3])
        : "r"(a[0]), "r"(a[1]), "r"(a[2]), "r"(a[3]), "r"(b[0]), "r"(b[1]));
}
__device__ __forceinline__ float tanh_ap(float x) {
    float y;
    asm("tanh.approx.f32 %0, %1;" : "=f"(y) : "f"(x));
    return y;
}
__device__ __forceinline__ float sig_ap(float x) { return 0.5f * tanh_ap(0.5f * x) + 0.5f; }
__device__ __forceinline__ void red_release_add(unsigned* p) {
    asm volatile("red.release.gpu.global.add.u32 [%0], %1;" :: "l"(p), "r"(1u) : "memory");
}
__device__ __forceinline__ unsigned ld_acquire(const unsigned* p) {
    unsigned v;
    asm volatile("ld.acquire.gpu.global.u32 %0, [%1];" : "=r"(v) : "l"(p) : "memory");
    return v;
}

// ---------------- K_init: zero barrier counters (replay-safe base) ----------------
__global__ void k_init()
{
    if (threadIdx.x < 8) ((unsigned*)g_cnt4)[threadIdx.x] = 0u;
}

// ---------------- K0: fp32 -> bf16 conversions ----------------
__global__ __launch_bounds__(256, 4) void k0_cvt_x(const float* __restrict__ xf)
{
    size_t n4 = (size_t)NROW * EMB / 4;
    for (size_t i = (size_t)blockIdx.x * 256 + threadIdx.x; i < n4;
         i += (size_t)gridDim.x * 256) {
        float4 v = ((const float4*)xf)[i];
        union { __nv_bfloat162 b2[2]; uint2 u2; } o;
        o.b2[0] = __floats2bfloat162_rn(v.x, v.y);
        o.b2[1] = __floats2bfloat162_rn(v.z, v.w);
        ((uint2*)g_xbf)[i] = o.u2;
    }
}
__global__ __launch_bounds__(256, 4) void k0_cvt_w(const float* __restrict__ wf,
                                                   const float* __restrict__ wb)
{
    size_t n2 = (size_t)G4 * EMB / 2;
    for (size_t i = (size_t)blockIdx.x * 256 + threadIdx.x; i < n2;
         i += (size_t)gridDim.x * 256) {
        float2 v = ((const float2*)wf)[i];
        ((__nv_bfloat162*)g_wbf)[i] = __float22bfloat162_rn(v);
        float2 u = ((const float2*)wb)[i];
        ((__nv_bfloat162*)g_wbf)[n2 + i] = __float22bfloat162_rn(u);
    }
}
__global__ __launch_bounds__(256, 4) void k0_cvt_whh(const float* __restrict__ wf,
                                                     const float* __restrict__ wb)
{
    size_t n2 = (size_t)G4 * HID / 2;
    for (size_t i = (size_t)blockIdx.x * 256 + threadIdx.x; i < n2;
         i += (size_t)gridDim.x * 256) {
        float2 v = ((const float2*)wf)[i];
        ((__nv_bfloat162*)g_whhbf)[i] = __float22bfloat162_rn(v);
        float2 u = ((const float2*)wb)[i];
        ((__nv_bfloat162*)g_whhbf)[n2 + i] = __float22bfloat162_rn(u);
    }
}

// ---------------- K1: input projection, mma.sync bf16 HMMA, 3-stage pipeline ----------------
#define KC     64
#define NSTG   (EMB / KC)      // 12
#define LDA    72              // bf16 elements per padded row
#define TILE_BYTES (128 * LDA * 2)   // 18432

__global__ __launch_bounds__(256)
void k1_inproj(const float* __restrict__ bf, const float* __restrict__ bb2)
{
    extern __shared__ __align__(16) char sm1[];
    uint32_t sbase = smem_u32(sm1);
    __shared__ float sbias[128];

    const int tid  = threadIdx.x;
    const int lane = tid & 31;
    const int wid  = tid >> 5;
    const int m0 = blockIdx.y * 128;
    const int n0 = blockIdx.x * 128;

    if (tid < 128) {
        int n = n0 + tid;
        sbias[tid] = (n < G4) ? bf[n] : bb2[n - G4];
    }

    const __nv_bfloat16* gA = g_xbf + (size_t)m0 * EMB;
    const __nv_bfloat16* gB = g_wbf + (size_t)n0 * EMB;
    const int q0 = tid * 4;

    auto stage = [&](int s, int buf) {
        uint32_t sa = sbase + buf * 2 * TILE_BYTES;
        uint32_t sb = sa + TILE_BYTES;
#pragma unroll
        for (int i = 0; i < 4; ++i) {
            int q = q0 + i;
            int row = q >> 3, cc = q & 7;
            uint32_t off = (uint32_t)row * (LDA * 2) + cc * 16;
            cp_async16(sa + off, gA + (size_t)row * EMB + s * KC + cc * 8);
            cp_async16(sb + off, gB + (size_t)row * EMB + s * KC + cc * 8);
        }
        cp_commit();
    };

    float acc[16][4];
#pragma unroll
    for (int i = 0; i < 16; ++i)
#pragma unroll
        for (int j = 0; j < 4; ++j) acc[i][j] = 0.f;

    const int warp_m = wid >> 2;
    const int warp_n = wid & 3;
    const int m_w = warp_m * 64;
    const int n_w = warp_n * 32;

    stage(0, 0);
    stage(1, 1);

    for (int s = 0; s < NSTG; ++s) {
        int buf = s % 3;
        if (s + 2 < NSTG) { stage(s + 2, (s + 2) % 3); cp_wait2(); }
        else if (s + 1 < NSTG) cp_wait1();
        else cp_wait0();
        __syncthreads();

        uint32_t sa = sbase + buf * 2 * TILE_BYTES;
        uint32_t sb = sa + TILE_BYTES;

#pragma unroll
        for (int kk = 0; kk < KC / 16; ++kk) {
            const int k0 = kk * 16;
            uint32_t af[4][4];
#pragma unroll
            for (int mi = 0; mi < 4; ++mi) {
                uint32_t addr = sa + ((uint32_t)(m_w + mi * 16 + (lane & 15)) * (LDA * 2))
                                   + ((uint32_t)(k0 + (lane >> 4) * 8) * 2);
                ldsm_x4(af[mi][0], af[mi][1], af[mi][2], af[mi][3], addr);
            }
            uint32_t bfrg[4][2];
#pragma unroll
            for (int p = 0; p < 2; ++p) {
                uint32_t nrow = (uint32_t)(n_w + p * 16 + ((lane >> 4) & 1) * 8 + (lane & 7));
                uint32_t kcol = (uint32_t)(k0 + ((lane >> 3) & 1) * 8);
                uint32_t addr = sb + nrow * (LDA * 2) + kcol * 2;
                uint32_t r0, r1, r2, r3;
                ldsm_x4(r0, r1, r2, r3, addr);
                bfrg[p * 2 + 0][0] = r0; bfrg[p * 2 + 0][1] = r1;
                bfrg[p * 2 + 1][0] = r2; bfrg[p * 2 + 1][1] = r3;
            }
#pragma unroll
            for (int mi = 0; mi < 4; ++mi)
#pragma unroll
                for (int ni = 0; ni < 4; ++ni)
                    mma_bf16(acc[mi * 4 + ni], af[mi], bfrg[ni]);
        }
        __syncthreads();
    }

#pragma unroll
    for (int mi = 0; mi < 4; ++mi) {
#pragma unroll
        for (int ni = 0; ni < 4; ++ni) {
            int mbase = m0 + m_w + mi * 16 + (lane >> 2);
            int nbase = n0 + n_w + ni * 8 + 2 * (lane & 3);
            int dir = nbase >> 11, g = nbase & 2047;
            float bia0 = sbias[nbase - n0], bia1 = sbias[nbase - n0 + 1];
#pragma unroll
            for (int rr = 0; rr < 2; ++rr) {
                int m = mbase + rr * 8;
                int b = m >> 9, t = m & 511;
                __nv_bfloat162 v = __floats2bfloat162_rn(
                    acc[mi * 4 + ni][rr * 2 + 0] + bia0,
                    acc[mi * 4 + ni][rr * 2 + 1] + bia1);
                *(__nv_bfloat162*)&g_xpbf[(((size_t)dir * SS + t) * BB + b) * G4 + g] = v;
            }
        }
    }
}

// ---------------- K2: persistent BiLSTM recurrence ----------------
// Four independent warp-level recurrence chains per CTA (batch quarters);
// release-add / acquire-load handoff, hybrid poll; h staging in 4 k-chunks
// overlapped with the HMMA chain. xp is bf16 (halved read traffic).
#define LDB 520    // bf16 per padded SMEM row (1040B, 16B-aligned, ldmatrix conflict-free)

__global__ __launch_bounds__(128, 1)
void k2_lstm_tc()
{
    extern __shared__ __align__(16) char sm2[];
    __nv_bfloat16* swb = (__nv_bfloat16*)sm2;      // [32][LDB] weights (persistent, read-only after load)
    __nv_bfloat16* shb = swb + 32 * LDB;           // [64][LDB] h tile; warp w owns rows [16w,16w+16)
    const uint32_t sw_u = smem_u32(swb);
    const uint32_t sh_u = smem_u32(shb);

    const int dir = blockIdx.x >> 6;
    const int ug  = blockIdx.x & 63;
    const int tid = threadIdx.x, lane = tid & 31, wid = tid >> 5;

    // load this CTA's 32 gate rows (gl = gate*8 + ul), k-major
    const __nv_bfloat16* wsrc = g_whhbf + (size_t)dir * G4 * HID;
    for (int i = tid; i < 32 * (HID / 8); i += 128) {
        int gl = i >> 6, cc = i & 63;
        int grow = (gl >> 3) * HID + ug * 8 + (gl & 7);
        *(uint4*)&swb[gl * LDB + cc * 8] = *(const uint4*)&wsrc[(size_t)grow * HID + cc * 8];
    }
    __syncthreads();   // weights visible to all warps; last CTA-wide sync

    float creg[4] = {0.f, 0.f, 0.f, 0.f};          // cell state, [r*2+e], register-resident
    const int brow = wid * 16 + (lane >> 2);       // batch row (+0 / +8)
    const int ul0  = 2 * (lane & 3);               // unit pair within group
    const int jcol = ug * 8 + ul0;                 // global hidden index (even)

    unsigned* cnt = &g_cnt4[dir][wid];

    for (int s = 0; s < SS; ++s) {
        const int t = dir ? (SS - 1 - s) : s;

        // prefetch xp (bf16, barrier-independent) — latency hidden behind the wait
        const __nv_bfloat16* xpb = g_xpbf + (((size_t)dir * SS + t) * BB) * G4;
        __nv_bfloat162 xv[2][4];
#pragma unroll
        for (int r = 0; r < 2; ++r)
#pragma unroll
            for (int gate = 0; gate < 4; ++gate)
                xv[r][gate] = __ldg((const __nv_bfloat162*)&xpb[(size_t)(brow + r * 8) * G4
                                                                + gate * HID + jcol]);

        float acc[4][4];                            // [gate][r*2+e]
#pragma unroll
        for (int a = 0; a < 4; ++a)
#pragma unroll
            for (int bq = 0; bq < 4; ++bq) acc[a][bq] = 0.f;

        if (s > 0) {
            // wait: all 64 counterpart warps (same wid) published h(s-1)
            if (lane == 0) {
                const unsigned tgt = 64u * (unsigned)s;
                int spins = 0;
                while ((int)(ld_acquire(cnt) - tgt) < 0) {
                    if (++spins > 64) __nanosleep(32);   // yield under skew; no unbounded hard spin
                }
            }
            __syncwarp();

            // stage own 16 batch rows (16KB) in 4 k-chunks; all issued now,
            // each chunk's completion awaited just before its MMA block.
            const int t_prev = dir ? (t + 1) : (t - 1);
            const __nv_bfloat16* hsrc = g_hallbf + ((size_t)dir * SS + t_prev) * BB * HID;
#pragma unroll
            for (int g = 0; g < 4; ++g) {
#pragma unroll
                for (int i = 0; i < 8; ++i) {
                    int q = i * 32 + lane;          // 0..255: 16 rows x 16 chunks of 16B
                    int row = wid * 16 + (q >> 4), cc = q & 15;
                    cp_async16(sh_u + (uint32_t)row * (LDB * 2) + (uint32_t)(g * 256 + cc * 16),
                               hsrc + (size_t)row * HID + g * 128 + cc * 8);
                }
                cp_commit();
            }

#pragma unroll
            for (int g = 0; g < 4; ++g) {
                if (g == 0) cp_waitn<3>();
                else if (g == 1) cp_waitn<2>();
                else if (g == 2) cp_waitn<1>();
                else cp_waitn<0>();
                __syncwarp();
#pragma unroll
                for (int kq = 0; kq < 8; ++kq) {
                    const int k0 = g * 128 + kq * 16;
                    uint32_t af[4];
                    {
                        uint32_t addr = sh_u + (uint32_t)(wid * 16 + (lane & 15)) * (LDB * 2)
                                             + (uint32_t)(k0 + (lane >> 4) * 8) * 2;
                        ldsm_x4(af[0], af[1], af[2], af[3], addr);
                    }
                    uint32_t bfrg[4][2];
#pragma unroll
                    for (int p = 0; p < 2; ++p) {
                        uint32_t nrow = (uint32_t)(p * 16 + ((lane >> 4) & 1) * 8 + (lane & 7));
                        uint32_t kcol = (uint32_t)(k0 + ((lane >> 3) & 1) * 8);
                        uint32_t addr = sw_u + nrow * (LDB * 2) + kcol * 2;
                        uint32_t r0, r1, r2, r3;
                        ldsm_x4(r0, r1, r2, r3, addr);
                        bfrg[p * 2 + 0][0] = r0; bfrg[p * 2 + 0][1] = r1;
                        bfrg[p * 2 + 1][0] = r2; bfrg[p * 2 + 1][1] = r3;
                    }
#pragma unroll
                    for (int ni = 0; ni < 4; ++ni) mma_bf16(acc[ni], af, bfrg[ni]);
                }
            }
        }

        // add prefetched xp, register-local cell update (MUFU), store h
        __nv_bfloat16* hall = g_hallbf + ((size_t)dir * SS + t) * BB * HID;
#pragma unroll
        for (int r = 0; r < 2; ++r) {
            int b = brow + r * 8;
            float hv[2];
#pragma unroll
            for (int e = 0; e < 2; ++e) {
                int q = r * 2 + e;
                float pi = acc[0][q] + (e ? __bfloat162float(xv[r][0].y) : __bfloat162float(xv[r][0].x));
                float pf = acc[1][q] + (e ? __bfloat162float(xv[r][1].y) : __bfloat162float(xv[r][1].x));
                float pg = acc[2][q] + (e ? __bfloat162float(xv[r][2].y) : __bfloat162float(xv[r][2].x));
                float po = acc[3][q] + (e ? __bfloat162float(xv[r][3].y) : __bfloat162float(xv[r][3].x));
                float i_ = sig_ap(pi);
                float f_ = sig_ap(pf);
                float g_ = tanh_ap(pg);
                float o_ = sig_ap(po);
                float c = f_ * creg[q] + i_ * g_;
                creg[q] = c;
                hv[e] = o_ * tanh_ap(c);
            }
            __nv_bfloat162 hb2 = __floats2bfloat162_rn(hv[0], hv[1]);
            *(__nv_bfloat162*)&hall[(size_t)b * HID + jcol] = hb2;
        }

        // publish: release-add orders the h stores, fire-and-forget, no MEMBAR
        __syncwarp();
        if (lane == 0) red_release_add(cnt);
    }
}

// ---------------- K3: emissions (bf16 h) ----------------
__global__ __launch_bounds__(256, 1)
void k3_emis(const float* __restrict__ wout, const float* __restrict__ bout)
{
    __shared__ float sw[NTAG][2 * HID];
    for (int i = threadIdx.x; i < NTAG * 2 * HID; i += 256)
        sw[i / (2 * HID)][i % (2 * HID)] = wout[i];
    __syncthreads();

    int warp = blockIdx.x * 8 + (threadIdx.x >> 5);
    int lane = threadIdx.x & 31;
    int t = warp >> 6, b = warp & 63;

    const __nv_bfloat16* hf = g_hallbf + (((size_t)0 * SS + t) * BB + b) * HID;
    const __nv_bfloat16* hb = g_hallbf + (((size_t)1 * SS + t) * BB + b) * HID;

    float acc[NTAG];
#pragma unroll
    for (int q = 0; q < NTAG; ++q) acc[q] = 0.f;

    for (int k2 = lane; k2 < HID / 2; k2 += 32) {
        __nv_bfloat162 a2 = *(const __nv_bfloat162*)&hf[2 * k2];
        __nv_bfloat162 c2 = *(const __nv_bfloat162*)&hb[2 * k2];
        float f0 = __bfloat162float(a2.x), f1 = __bfloat162float(a2.y);
        float g0 = __bfloat162float(c2.x), g1 = __bfloat162float(c2.y);
#pragma unroll
        for (int q = 0; q < NTAG; ++q) {
            acc[q] = fmaf(f0, sw[q][2 * k2], acc[q]);
            acc[q] = fmaf(f1, sw[q][2 * k2 + 1], acc[q]);
            acc[q] = fmaf(g0, sw[q][HID + 2 * k2], acc[q]);
            acc[q] = fmaf(g1, sw[q][HID + 2 * k2 + 1], acc[q]);
        }
    }
#pragma unroll
    for (int q = 0; q < NTAG; ++q)
        for (int off = 16; off; off >>= 1)
            acc[q] += __shfl_down_sync(0xffffffffu, acc[q], off);
    if (lane == 0) {
#pragma unroll
        for (int q = 0; q < NTAG; ++q)
            g_emis[((size_t)t * BB + b) * NTAG + q] = acc[q] + bout[q];
    }
}

// ---------------- K4: CRF (fast exp/log; 1 warp per CTA, 64 CTAs -> MUFU spread) ----------------
__global__ __launch_bounds__(32, 1)
void k4_crf(const int* __restrict__ mask, const int* __restrict__ tags,
            const float* __restrict__ st, const float* __restrict__ et,
            const float* __restrict__ tr)
{
    const int b = blockIdx.x;          // 0..63
    const int lane = threadIdx.x & 31;
    const int* mb = mask + b * SS;
    const int* tg = tags + b * SS;

    float numpart = 0.f, mpart = 0.f;
    for (int t = lane; t < SS; t += 32) {
        float m = (float)mb[t];
        mpart += m;
        if (t >= 1)
            numpart += m * (tr[tg[t - 1] * NTAG + tg[t]] +
                            g_emis[((size_t)t * BB + b) * NTAG + tg[t]]);
    }
    for (int off = 16; off; off >>= 1) {
        numpart += __shfl_xor_sync(0xffffffffu, numpart, off);
        mpart   += __shfl_xor_sync(0xffffffffu, mpart, off);
    }

    float tc[NTAG];
#pragma unroll
    for (int j = 0; j < NTAG; ++j)
        tc[j] = (lane < NTAG) ? tr[j * NTAG + lane] : 0.f;

    float alpha = (lane < NTAG)
        ? st[lane] + g_emis[((size_t)0 * BB + b) * NTAG + lane]
        : -1e30f;

    for (int t = 1; t < SS; ++t) {
        float e = (lane < NTAG) ? g_emis[((size_t)t * BB + b) * NTAG + lane] : 0.f;
        float v[NTAG];
        float mx = -1e30f;
#pragma unroll
        for (int j = 0; j < NTAG; ++j) {
            v[j] = __shfl_sync(0xffffffffu, alpha, j) + tc[j];
            mx = fmaxf(mx, v[j]);
        }
        float sum = 0.f;
#pragma unroll
        for (int j = 0; j < NTAG; ++j) sum += __expf(v[j] - mx);
        float nxt = mx + __logf(sum) + e;
        alpha = (mb[t] > 0) ? nxt : alpha;
    }

    float vden = (lane < NTAG) ? alpha + et[lane] : -1e30f;
    float mx = vden;
    for (int off = 16; off; off >>= 1) mx = fmaxf(mx, __shfl_xor_sync(0xffffffffu, mx, off));
    float se = (lane < NTAG) ? __expf(vden - mx) : 0.f;
    for (int off = 16; off; off >>= 1) se += __shfl_xor_sync(0xffffffffu, se, off);
    float den = mx + __logf(se);

    if (lane == 0) {
        int t0 = tg[0];
        float num = numpart + st[t0] + g_emis[((size_t)0 * BB + b) * NTAG + t0];
        int li = (int)(mpart + 0.5f) - 1;
        num += et[tg[li]];
        g_llh[b]  = num - den;
        g_msum[b] = mpart;
    }
}

// ---------------- K5: deterministic final reduce ----------------
__global__ void k5_reduce(float* out)
{
    if (threadIdx.x == 0 && blockIdx.x == 0) {
        float sn = 0.f, sm = 0.f;
        for (int b = 0; b < BB; ++b) { sn += g_llh[b]; sm += g_msum[b]; }
        out[0] = -(sn / sm);
    }
}

// ---------------- launch ----------------
extern "C" void kernel_launch(void* const* d_in, const int* in_sizes, int n_in,
                              void* d_out, int out_size)
{
    const float* x    = (const float*)d_in[0];
    const int*   mask = (const int*)  d_in[1];
    const int*   tags = (const int*)  d_in[2];
    const float* wihf = (const float*)d_in[3];
    const float* whhf = (const float*)d_in[4];
    const float* bf   = (const float*)d_in[5];
    const float* wihb = (const float*)d_in[6];
    const float* whhb = (const float*)d_in[7];
    const float* bb2  = (const float*)d_in[8];
    const float* wout = (const float*)d_in[9];
    const float* bout = (const float*)d_in[10];
    const float* st   = (const float*)d_in[11];
    const float* et   = (const float*)d_in[12];
    const float* tr   = (const float*)d_in[13];
    float* out = (float*)d_out;

    const int smem1 = 6 * TILE_BYTES;                        // 110592: 3-stage A|B
    const int smem2 = 96 * LDB * (int)sizeof(__nv_bfloat16); // 99840
    static int inited = 0;
    if (!inited) {
        cudaFuncSetAttribute(k1_inproj, cudaFuncAttributeMaxDynamicSharedMemorySize, smem1);
        cudaFuncSetAttribute(k2_lstm_tc, cudaFuncAttributeMaxDynamicSharedMemorySize, smem2);
        inited = 1;
    }

    k_init<<<1, 32>>>();
    k0_cvt_x<<<2048, 256>>>(x);
    k0_cvt_w<<<512, 256>>>(wihf, wihb);
    k0_cvt_whh<<<512, 256>>>(whhf, whhb);
    k1_inproj<<<dim3(NCOL / 128, NROW / 128), 256, smem1>>>(bf, bb2);
    k2_lstm_tc<<<128, 128, smem2>>>();
    k3_emis<<<NROW / 8, 256>>>(wout, bout);
    k4_crf<<<BB, 32>>>(mask, tags, st, et, tr);
    k5_reduce<<<1, 32>>>(out);
}